// round 13
// baseline (speedup 1.0000x reference)
#include <cuda_runtime.h>
#include <math.h>

// HybridEulerIntegrator via tabulated dk(x,a), chain-minimized scan.
// Table rows indexed by the float bits of v=1+|a| (7 mantissa bits/octave,
// 12 octaves, 1536 bins per sign -> 3072 rows per x-segment, 2 x-segments).
// Each row stores TWO cubics in x: C (dk at the row's lower-a edge) and
// D = C_next - C (difference to next row), so dk = polyC + fs*polyD needs a
// single row fetch (2 LDS.128 from independent 16B-stride arrays) and no
// row-pair subtract. All index math is integer-domain; fw/fs/x^2/rbase are
// computed off the a-dependency chain.

#define T_STEPS 2048
#define BATCH   16384
#define HIDDEN  64
#define NR      3072              // rows per x-segment (1536 neg + 1536 pos)
#define NPOLY   (2 * (NR + 1))    // fitted C rows incl. virtual top row, both segs
#define NTAB    (2 * NR)          // packed rows (both segs)
#define PF      8

__device__ float  g_nodes[NPOLY * 4];     // staging: dk at 4 x-nodes per fitted row
__device__ float4 g_Cfit[NPOLY];          // staging: fitted C cubics
__device__ float4 g_tabC[NTAB];           // packed C
__device__ float4 g_tabD[NTAB];           // packed D = C_next - C

// edge value for 7-bit mantissa bin k in [0,1536]: 2^(k>>7) * (1 + (k&127)/128)
__device__ __forceinline__ float edge_v7(int k) {
    return exp2f((float)(k >> 7)) * (1.0f + (float)(k & 127) * (1.0f / 128.0f));
}

// fitted-row r in [0, NR+1) per seg -> a at the row's lower-a edge.
// r >= 1536: a = edge(r-1536)-1 (a >= 0, r=NR maps to the virtual top edge)
// r <  1536: a = -(edge(1536-r)-1)
__device__ __forceinline__ float row_to_a(int r) {
    if (r >= 1536) return  edge_v7(r - 1536) - 1.0f;
    else           return -(edge_v7(1536 - r) - 1.0f);
}

__device__ __forceinline__ float node_x(int seg, int node) {
    const float lo = 0.5f * (float)seg;
    return lo + 0.5f * (0.5f + 0.5f * cosf((2.0f * node + 1.0f) * (float)M_PI / 8.0f));
}

// ---------------------------------------------------------------------------
// Build 1: dk at 4 Chebyshev x-nodes for each fitted row. NPOLY*4 threads.
// ---------------------------------------------------------------------------
__global__ void build_eval_kernel(const float* __restrict__ W1,
                                  const float* __restrict__ b1,
                                  const float* __restrict__ W2,
                                  const float* __restrict__ b2)
{
    const int tid = blockIdx.x * blockDim.x + threadIdx.x;
    if (tid >= NPOLY * 4) return;
    const int poly = tid >> 2;
    const int node = tid & 3;
    const int seg  = poly / (NR + 1);
    const int row  = poly - seg * (NR + 1);

    const float a = row_to_a(row);
    const float x = node_x(seg, node);

    float acc = b2[0];
    for (int j = 0; j < HIDDEN; j++) {
        float pre = fmaf(W1[j], x, fmaf(W1[HIDDEN + j], a, b1[j]));
        acc = fmaf(W2[j], tanhf(pre), acc);
    }
    g_nodes[tid] = acc;
}

// ---------------------------------------------------------------------------
// Build 2: fit cubic per row (Newton DD -> monomial).
// ---------------------------------------------------------------------------
__global__ void build_fit_kernel()
{
    const int poly = blockIdx.x * blockDim.x + threadIdx.x;
    if (poly >= NPOLY) return;
    const int seg = poly / (NR + 1);

    float xn[4], v[4];
#pragma unroll
    for (int k = 0; k < 4; k++) {
        xn[k] = node_x(seg, k);
        v[k]  = g_nodes[poly * 4 + k];
    }
#pragma unroll
    for (int j = 1; j < 4; j++)
#pragma unroll
        for (int i = 3; i >= j; i--)
            v[i] = (v[i] - v[i - 1]) / (xn[i] - xn[i - j]);

    float m[4];
    m[0] = v[3]; m[1] = 0.0f; m[2] = 0.0f; m[3] = 0.0f;
#pragma unroll
    for (int k = 2; k >= 0; k--) {
#pragma unroll
        for (int i = 3; i >= 1; i--)
            m[i] = m[i - 1] - xn[k] * m[i];
        m[0] = v[k] - xn[k] * m[0];
    }
    g_Cfit[poly] = make_float4(m[0], m[1], m[2], m[3]);
}

// ---------------------------------------------------------------------------
// Build 3: pack (C, D) tables. One thread per packed row.
// ---------------------------------------------------------------------------
__global__ void build_pack_kernel()
{
    const int i = blockIdx.x * blockDim.x + threadIdx.x;
    if (i >= NTAB) return;
    const int seg = i / NR;
    const int row = i - seg * NR;
    const int src = seg * (NR + 1) + row;

    const float4 c  = g_Cfit[src];
    const float4 cn = g_Cfit[src + 1];     // within-seg neighbor (virtual top exists)
    g_tabC[i] = c;
    g_tabD[i] = make_float4(cn.x - c.x, cn.y - c.y, cn.z - c.z, cn.w - c.w);
}

// ---------------------------------------------------------------------------
// Scan.
// ---------------------------------------------------------------------------
#define MBLOCK 128

__global__ void __launch_bounds__(MBLOCK)
scan_kernel(const float* __restrict__ x,
            const float* __restrict__ a0,
            float* __restrict__ out)
{
    extern __shared__ float4 sm[];          // [0..NTAB)=C, [NTAB..2*NTAB)=D
    for (int i = threadIdx.x; i < NTAB; i += MBLOCK) {
        sm[i]        = g_tabC[i];
        sm[NTAB + i] = g_tabD[i];
    }
    __syncthreads();

    const int e = blockIdx.x * MBLOCK + threadIdx.x;

    float a = a0[e];
    const float* xp = x + e;
    float*       op = out + e;

    float cur[PF], nxt[PF];
#pragma unroll
    for (int k = 0; k < PF; k++)
        cur[k] = __ldg(xp + k * BATCH);

    for (int tb = 0; tb < T_STEPS; tb += PF) {
        if (tb + PF < T_STEPS) {
#pragma unroll
            for (int k = 0; k < PF; k++)
                nxt[k] = __ldg(xp + (PF + k) * BATCH);
        }

        // Off-chain per-x precompute: x^2 and the row base (sign-pivot + x-seg).
        float xsq[PF];
        int   rbase[PF];
#pragma unroll
        for (int k = 0; k < PF; k++) {
            xsq[k]   = cur[k] * cur[k];
            rbase[k] = 1536 + ((cur[k] >= 0.5f) ? NR : 0);
        }

#pragma unroll
        for (int k = 0; k < PF; k++) {
            const float xt = cur[k];

            // --- critical chain: a -> row -> 2x LDS -> poly -> fma -> cube -> a ---
            const float v    = fabsf(a) + 1.0f;            // FADD (abs is free)
            const int   bits = __float_as_int(v);
            const int   sgn  = __float_as_int(a) >> 31;    // 0 / -1 (parallel)
            int t = bits >> 16;                            // exponent + 7 mantissa bits
            t = min(t, 16256 + 1535);                      // int-domain clamp
            const int idx = (t - 16256) ^ sgn;             // sign-mirrored bin
            const int r   = idx + rbase[k];                // row in [0, NTAB)

            const float4 Cc = sm[r];
            const float4 Dd = sm[NTAB + r];

            // Off the LDS latency: within-bin fraction (mirrored for a<0).
            const float fw = __int_as_float(((bits & 0xFFFF) << 7) | 0x3F800000) - 1.0f;
            const float fs = (sgn != 0) ? (1.0f - fw) : fw;

            const float pc = fmaf(fmaf(Cc.w, xt, Cc.z), xsq[k], fmaf(Cc.y, xt, Cc.x));
            const float pd = fmaf(fmaf(Dd.w, xt, Dd.z), xsq[k], fmaf(Dd.y, xt, Dd.x));
            const float dk = fmaf(fs, pd, pc);

            a = fmaf(0.001f * dk, dk * dk, a);

            op[k * (size_t)BATCH] = a;
        }

#pragma unroll
        for (int k = 0; k < PF; k++) cur[k] = nxt[k];
        xp += PF * BATCH;
        op += PF * (size_t)BATCH;
    }
}

extern "C" void kernel_launch(void* const* d_in, const int* in_sizes, int n_in,
                              void* d_out, int out_size)
{
    const float* x  = (const float*)d_in[0];
    const float* a0 = (const float*)d_in[1];
    const float* W1 = (const float*)d_in[2];
    const float* b1 = (const float*)d_in[3];
    const float* W2 = (const float*)d_in[4];
    const float* b2 = (const float*)d_in[5];
    float* out = (float*)d_out;

    build_eval_kernel<<<(NPOLY * 4 + 127) / 128, 128>>>(W1, b1, W2, b2);
    build_fit_kernel<<<(NPOLY + 127) / 128, 128>>>();
    build_pack_kernel<<<(NTAB + 127) / 128, 128>>>();

    const size_t smem = 2u * NTAB * sizeof(float4);   // 196608 B
    static int smem_set = 0;
    if (!smem_set) {
        cudaFuncSetAttribute(scan_kernel,
                             cudaFuncAttributeMaxDynamicSharedMemorySize,
                             (int)smem);
        smem_set = 1;
    }
    scan_kernel<<<BATCH / MBLOCK, MBLOCK, smem>>>(x, a0, out);
}

// round 14
// speedup vs baseline: 1.1538x; 1.1538x over previous
#include <cuda_runtime.h>
#include <math.h>

// HybridEulerIntegrator via tabulated dk(x,a).
// R12 memory pattern (two ADJACENT 16B LDS per step) + chain cuts:
//  - interleaved stored-diff rows: tab[2r]=C, tab[2r+1]=D=C_next-C
//    -> dk = fma(fs, pd, pc), no on-chain subtract
//  - int-domain index, sign fold via (sgn & 32512), single IADD3
//  - cbrt(0.001)=0.1 folded into coeffs -> a = fma(dk*dk, dk, a)
// 7 mantissa bits/octave (1536 bins/sign), 2 x-segments, deg-3 in x.

#define T_STEPS 2048
#define BATCH   16384
#define HIDDEN  64
#define NR      3072              // rows per x-segment (1536 neg + 1536 pos)
#define NFIT    (2 * (NR + 1))    // fitted rows incl. virtual top, both segs
#define NTAB    (2 * NR)          // packed logical rows (both segs)
#define PF      8

__device__ float  g_nodes[NFIT * 4];     // staging: dk at 4 x-nodes per fitted row
__device__ float4 g_Cfit[NFIT];          // staging: fitted cubics
__device__ float4 g_tab[2 * NTAB];       // interleaved: [2r]=0.1*C, [2r+1]=0.1*D

// edge value for 7-bit mantissa bin k in [0,1536]: 2^(k>>7) * (1 + (k&127)/128)
__device__ __forceinline__ float edge_v7(int k) {
    return exp2f((float)(k >> 7)) * (1.0f + (float)(k & 127) * (1.0f / 128.0f));
}

// fitted-row r in [0, NR+1) per seg -> a at the row's lower-a edge.
__device__ __forceinline__ float row_to_a(int r) {
    if (r >= 1536) return  edge_v7(r - 1536) - 1.0f;
    else           return -(edge_v7(1536 - r) - 1.0f);
}

__device__ __forceinline__ float node_x(int seg, int node) {
    const float lo = 0.5f * (float)seg;
    return lo + 0.5f * (0.5f + 0.5f * cosf((2.0f * node + 1.0f) * (float)M_PI / 8.0f));
}

// ---------------------------------------------------------------------------
// Build 1: dk at 4 Chebyshev x-nodes for each fitted row.
// ---------------------------------------------------------------------------
__global__ void build_eval_kernel(const float* __restrict__ W1,
                                  const float* __restrict__ b1,
                                  const float* __restrict__ W2,
                                  const float* __restrict__ b2)
{
    const int tid = blockIdx.x * blockDim.x + threadIdx.x;
    if (tid >= NFIT * 4) return;
    const int poly = tid >> 2;
    const int node = tid & 3;
    const int seg  = poly / (NR + 1);
    const int row  = poly - seg * (NR + 1);

    const float a = row_to_a(row);
    const float x = node_x(seg, node);

    float acc = b2[0];
    for (int j = 0; j < HIDDEN; j++) {
        float pre = fmaf(W1[j], x, fmaf(W1[HIDDEN + j], a, b1[j]));
        acc = fmaf(W2[j], tanhf(pre), acc);
    }
    g_nodes[tid] = acc;
}

// ---------------------------------------------------------------------------
// Build 2: fit cubic per fitted row (Newton DD -> monomial).
// ---------------------------------------------------------------------------
__global__ void build_fit_kernel()
{
    const int poly = blockIdx.x * blockDim.x + threadIdx.x;
    if (poly >= NFIT) return;
    const int seg = poly / (NR + 1);

    float xn[4], v[4];
#pragma unroll
    for (int k = 0; k < 4; k++) {
        xn[k] = node_x(seg, k);
        v[k]  = g_nodes[poly * 4 + k];
    }
#pragma unroll
    for (int j = 1; j < 4; j++)
#pragma unroll
        for (int i = 3; i >= j; i--)
            v[i] = (v[i] - v[i - 1]) / (xn[i] - xn[i - j]);

    float m[4];
    m[0] = v[3]; m[1] = 0.0f; m[2] = 0.0f; m[3] = 0.0f;
#pragma unroll
    for (int k = 2; k >= 0; k--) {
#pragma unroll
        for (int i = 3; i >= 1; i--)
            m[i] = m[i - 1] - xn[k] * m[i];
        m[0] = v[k] - xn[k] * m[0];
    }
    g_Cfit[poly] = make_float4(m[0], m[1], m[2], m[3]);
}

// ---------------------------------------------------------------------------
// Build 3: pack interleaved (0.1*C, 0.1*D) rows.
// ---------------------------------------------------------------------------
__global__ void build_pack_kernel()
{
    const int i = blockIdx.x * blockDim.x + threadIdx.x;
    if (i >= NTAB) return;
    const int seg = i / NR;
    const int row = i - seg * NR;
    const int src = seg * (NR + 1) + row;

    const float4 c  = g_Cfit[src];
    const float4 cn = g_Cfit[src + 1];     // within-seg neighbor (virtual top exists)
    const float  S  = 0.1f;                // cbrt(0.001)
    g_tab[2 * i]     = make_float4(S * c.x, S * c.y, S * c.z, S * c.w);
    g_tab[2 * i + 1] = make_float4(S * (cn.x - c.x), S * (cn.y - c.y),
                                   S * (cn.z - c.z), S * (cn.w - c.w));
}

// ---------------------------------------------------------------------------
// Scan.
// ---------------------------------------------------------------------------
#define MBLOCK 128

__global__ void __launch_bounds__(MBLOCK)
scan_kernel(const float* __restrict__ x,
            const float* __restrict__ a0,
            float* __restrict__ out)
{
    extern __shared__ float4 sm[];          // interleaved [2r]=C, [2r+1]=D
    for (int i = threadIdx.x; i < 2 * NTAB; i += MBLOCK)
        sm[i] = g_tab[i];
    __syncthreads();

    const int e = blockIdx.x * MBLOCK + threadIdx.x;

    float a = a0[e];
    const float* xp = x + e;
    float*       op = out + e;

    float cur[PF], nxt[PF];
#pragma unroll
    for (int k = 0; k < PF; k++)
        cur[k] = __ldg(xp + k * BATCH);

    for (int tb = 0; tb < T_STEPS; tb += PF) {
        if (tb + PF < T_STEPS) {
#pragma unroll
            for (int k = 0; k < PF; k++)
                nxt[k] = __ldg(xp + (PF + k) * BATCH);
        }

        // Off-chain per-x precompute: x^2 and the fused row base.
        // rbase = segNR - 14720  (pos-side constant; neg side adds 32512 via sgn mask)
        float xsq[PF];
        int   rbase[PF];
#pragma unroll
        for (int k = 0; k < PF; k++) {
            xsq[k]   = cur[k] * cur[k];
            rbase[k] = ((cur[k] >= 0.5f) ? NR : 0) - 14720;
        }

#pragma unroll
        for (int k = 0; k < PF; k++) {
            const float xt = cur[k];

            // --- critical chain: a -> row -> 2 adjacent LDS -> poly -> fma -> cube ---
            const float v    = fabsf(a) + 1.0f;          // FADD (|.| free)
            const int   bits = __float_as_int(v);
            const int   sgn  = __float_as_int(a) >> 31;  // 0 / -1 (parallel)
            int t = bits >> 16;                          // exp + 7 mantissa bits
            t = min(t, 17791);                           // int clamp (top bin)
            // row: pos: t-16256+1536+segNR ; neg: 17791-t+segNR  (mirrored)
            const int row = (t ^ sgn) + rbase[k] + (sgn & 32512);

            const float4 Cc = sm[2 * row];
            const float4 Dd = sm[2 * row + 1];

            // Off the LDS latency: within-bin fraction (mirrored for a<0).
            const float fw = __int_as_float(((bits & 0xFFFF) << 7) | 0x3F800000) - 1.0f;
            const float fs = (sgn != 0) ? (1.0f - fw) : fw;

            const float pc = fmaf(fmaf(Cc.w, xt, Cc.z), xsq[k], fmaf(Cc.y, xt, Cc.x));
            const float pd = fmaf(fmaf(Dd.w, xt, Dd.z), xsq[k], fmaf(Dd.y, xt, Dd.x));
            const float dk = fmaf(fs, pd, pc);           // dk' = 0.1*dk

            a = fmaf(dk * dk, dk, a);                    // a += (0.1*dk)^3 = 0.001*dk^3

            op[k * (size_t)BATCH] = a;
        }

#pragma unroll
        for (int k = 0; k < PF; k++) cur[k] = nxt[k];
        xp += PF * BATCH;
        op += PF * (size_t)BATCH;
    }
}

extern "C" void kernel_launch(void* const* d_in, const int* in_sizes, int n_in,
                              void* d_out, int out_size)
{
    const float* x  = (const float*)d_in[0];
    const float* a0 = (const float*)d_in[1];
    const float* W1 = (const float*)d_in[2];
    const float* b1 = (const float*)d_in[3];
    const float* W2 = (const float*)d_in[4];
    const float* b2 = (const float*)d_in[5];
    float* out = (float*)d_out;

    build_eval_kernel<<<(NFIT * 4 + 127) / 128, 128>>>(W1, b1, W2, b2);
    build_fit_kernel<<<(NFIT + 127) / 128, 128>>>();
    build_pack_kernel<<<(NTAB + 127) / 128, 128>>>();

    const size_t smem = 2u * NTAB * sizeof(float4);   // 196608 B
    static int smem_set = 0;
    if (!smem_set) {
        cudaFuncSetAttribute(scan_kernel,
                             cudaFuncAttributeMaxDynamicSharedMemorySize,
                             (int)smem);
        smem_set = 1;
    }
    scan_kernel<<<BATCH / MBLOCK, MBLOCK, smem>>>(x, a0, out);
}

// round 15
// speedup vs baseline: 1.3234x; 1.1470x over previous
#include <cuda_runtime.h>
#include <math.h>

// HybridEulerIntegrator via tabulated dk(x,a) with windowed a-bin reuse.
// Table: 3072 a-rows (7 mantissa bits/octave, 12 octaves, 1536 per sign),
// each row = degree-5 poly in x over full [0,1): C (row lower edge) and
// D = C_next - C, 12 floats = 48B = 3 adjacent LDS.128. Coeffs pre-scaled by
// 0.1 = cbrt(0.001).
// Scan: fetch the row once per 4-step WINDOW; within the window the a-lerp
// fraction is extrapolated linearly in true a: u = fma(a, invW, nb) (exact at
// the window head, 2nd-order error after). Per-step chain: FFMA(u) ->
// FFMA(dk) -> FMUL -> FFMA(a) = ~16 cyc; index+LDS amortized over 4 steps.

#define T_STEPS 2048
#define BATCH   16384
#define HIDDEN  64
#define NROW    3072            // packed a-rows
#define NFIT    (NROW + 1)      // fitted rows incl. virtual top edge
#define NDEG    6               // degree-5 poly: 6 coefficients
#define PF      8
#define WIN     4

__device__ float  g_nodes[NFIT * NDEG];  // staging: dk at 6 x-nodes per fitted row
__device__ float  g_Cfit[NFIT * NDEG];   // staging: fitted monomial coeffs
__device__ float4 g_tab[3 * NROW];       // packed rows (0.1*C0..C5, 0.1*D0..D5)

// edge value for 7-bit mantissa bin k in [0,1536]: 2^(k>>7) * (1 + (k&127)/128)
__device__ __forceinline__ float edge_v7(int k) {
    return exp2f((float)(k >> 7)) * (1.0f + (float)(k & 127) * (1.0f / 128.0f));
}

// fitted-row r in [0, NFIT) -> a at the row's lower-a edge.
__device__ __forceinline__ float row_to_a(int r) {
    if (r >= 1536) return  edge_v7(r - 1536) - 1.0f;
    else           return -(edge_v7(1536 - r) - 1.0f);
}

// Chebyshev nodes on [0,1], 6 nodes.
__device__ __forceinline__ float node_x(int node) {
    return 0.5f + 0.5f * cosf((2.0f * node + 1.0f) * (float)M_PI / 12.0f);
}

// ---------------------------------------------------------------------------
// Build 1: dk at 6 Chebyshev x-nodes for each fitted row. NFIT*6 threads.
// ---------------------------------------------------------------------------
__global__ void build_eval_kernel(const float* __restrict__ W1,
                                  const float* __restrict__ b1,
                                  const float* __restrict__ W2,
                                  const float* __restrict__ b2)
{
    const int tid = blockIdx.x * blockDim.x + threadIdx.x;
    if (tid >= NFIT * NDEG) return;
    const int row  = tid / NDEG;
    const int node = tid - row * NDEG;

    const float a = row_to_a(row);
    const float x = node_x(node);

    float acc = b2[0];
    for (int j = 0; j < HIDDEN; j++) {
        float pre = fmaf(W1[j], x, fmaf(W1[HIDDEN + j], a, b1[j]));
        acc = fmaf(W2[j], tanhf(pre), acc);
    }
    g_nodes[tid] = acc;
}

// ---------------------------------------------------------------------------
// Build 2: fit degree-5 poly per fitted row (Newton DD -> monomial).
// ---------------------------------------------------------------------------
__global__ void build_fit_kernel()
{
    const int row = blockIdx.x * blockDim.x + threadIdx.x;
    if (row >= NFIT) return;

    float xn[NDEG], v[NDEG];
#pragma unroll
    for (int k = 0; k < NDEG; k++) {
        xn[k] = node_x(k);
        v[k]  = g_nodes[row * NDEG + k];
    }
#pragma unroll
    for (int j = 1; j < NDEG; j++)
#pragma unroll
        for (int i = NDEG - 1; i >= j; i--)
            v[i] = (v[i] - v[i - 1]) / (xn[i] - xn[i - j]);

    float m[NDEG];
    m[0] = v[NDEG - 1];
#pragma unroll
    for (int i = 1; i < NDEG; i++) m[i] = 0.0f;
#pragma unroll
    for (int k = NDEG - 2; k >= 0; k--) {
#pragma unroll
        for (int i = NDEG - 1; i >= 1; i--)
            m[i] = m[i - 1] - xn[k] * m[i];
        m[0] = v[k] - xn[k] * m[0];
    }
#pragma unroll
    for (int i = 0; i < NDEG; i++) g_Cfit[row * NDEG + i] = m[i];
}

// ---------------------------------------------------------------------------
// Build 3: pack rows: (0.1*C0..C5, 0.1*D0..D5) as 3 float4.
// ---------------------------------------------------------------------------
__global__ void build_pack_kernel()
{
    const int i = blockIdx.x * blockDim.x + threadIdx.x;
    if (i >= NROW) return;
    const float S = 0.1f;   // cbrt(0.001)

    float C[NDEG], D[NDEG];
#pragma unroll
    for (int k = 0; k < NDEG; k++) {
        const float c = g_Cfit[i * NDEG + k];
        C[k] = S * c;
        D[k] = S * (g_Cfit[(i + 1) * NDEG + k] - c);
    }
    g_tab[3 * i]     = make_float4(C[0], C[1], C[2], C[3]);
    g_tab[3 * i + 1] = make_float4(C[4], C[5], D[0], D[1]);
    g_tab[3 * i + 2] = make_float4(D[2], D[3], D[4], D[5]);
}

// ---------------------------------------------------------------------------
// Scan.
// ---------------------------------------------------------------------------
#define MBLOCK 128

__global__ void __launch_bounds__(MBLOCK)
scan_kernel(const float* __restrict__ x,
            const float* __restrict__ a0,
            float* __restrict__ out)
{
    extern __shared__ float4 sm[];          // 3 float4 per row
    for (int i = threadIdx.x; i < 3 * NROW; i += MBLOCK)
        sm[i] = g_tab[i];
    __syncthreads();

    const int e = blockIdx.x * MBLOCK + threadIdx.x;

    float a = a0[e];
    const float* xp = x + e;
    float*       op = out + e;

    float cur[PF], nxt[PF];
#pragma unroll
    for (int k = 0; k < PF; k++)
        cur[k] = __ldg(xp + k * BATCH);

    for (int tb = 0; tb < T_STEPS; tb += PF) {
        if (tb + PF < T_STEPS) {
#pragma unroll
            for (int k = 0; k < PF; k++)
                nxt[k] = __ldg(xp + (PF + k) * BATCH);
        }

        // Off-chain: x^3 per step.
        float x3[PF];
#pragma unroll
        for (int k = 0; k < PF; k++)
            x3[k] = cur[k] * cur[k] * cur[k];

#pragma unroll
        for (int w = 0; w < PF; w += WIN) {
            // ---- window head: index + row fetch (amortized over WIN steps) ----
            const float v    = fabsf(a) + 1.0f;
            const int   bits = __float_as_int(v);
            const int   sgn  = __float_as_int(a) >> 31;     // 0 / -1
            int t = bits >> 16;                             // exp + 7 mantissa bits
            t = min(t, 17791);                              // clamp to top bin
            const int row = ((t ^ sgn) + (sgn & 32512)) - 14720;

            const float4 P0 = sm[3 * row];
            const float4 P1 = sm[3 * row + 1];
            const float4 P2 = sm[3 * row + 2];

            // Linear model of the lerp fraction in TRUE a: u(a') = a'*invW + nb,
            // exact at the window head (u(a)=fs0), slope +invW for both signs.
            const float fw  = __int_as_float(((bits & 0xFFFF) << 7) | 0x3F800000) - 1.0f;
            const float fs0 = (sgn != 0) ? (1.0f - fw) : fw;
            const float invW = __int_as_float((261 - (bits >> 23)) << 23);
            const float nb   = fmaf(-a, invW, fs0);

            // Per-step polys pc/pd (off the a-chain; coeff map:
            // C0..C3=P0, C4=P1.x, C5=P1.y, D0=P1.z, D1=P1.w, D2..D5=P2).
            float pc[WIN], pd[WIN];
#pragma unroll
            for (int j = 0; j < WIN; j++) {
                const float xt = cur[w + j];
                const float xq = x3[w + j];
                pc[j] = fmaf(fmaf(fmaf(P1.y, xt, P1.x), xt, P0.w), xq,
                             fmaf(fmaf(P0.z, xt, P0.y), xt, P0.x));
                pd[j] = fmaf(fmaf(fmaf(P2.w, xt, P2.z), xt, P2.y), xq,
                             fmaf(fmaf(P2.x, xt, P1.w), xt, P1.z));
            }

            // ---- window body: 4 steps, ~16-cyc chain each ----
#pragma unroll
            for (int j = 0; j < WIN; j++) {
                const float u  = fmaf(a, invW, nb);
                const float dk = fmaf(u, pd[j], pc[j]);   // dk' = 0.1*dk
                a = fmaf(dk * dk, dk, a);                 // a += 0.001*dk^3
                op[(w + j) * (size_t)BATCH] = a;
            }
        }

#pragma unroll
        for (int k = 0; k < PF; k++) cur[k] = nxt[k];
        xp += PF * BATCH;
        op += PF * (size_t)BATCH;
    }
}

extern "C" void kernel_launch(void* const* d_in, const int* in_sizes, int n_in,
                              void* d_out, int out_size)
{
    const float* x  = (const float*)d_in[0];
    const float* a0 = (const float*)d_in[1];
    const float* W1 = (const float*)d_in[2];
    const float* b1 = (const float*)d_in[3];
    const float* W2 = (const float*)d_in[4];
    const float* b2 = (const float*)d_in[5];
    float* out = (float*)d_out;

    build_eval_kernel<<<(NFIT * NDEG + 127) / 128, 128>>>(W1, b1, W2, b2);
    build_fit_kernel<<<(NFIT + 127) / 128, 128>>>();
    build_pack_kernel<<<(NROW + 127) / 128, 128>>>();

    const size_t smem = 3u * NROW * sizeof(float4);   // 147456 B
    static int smem_set = 0;
    if (!smem_set) {
        cudaFuncSetAttribute(scan_kernel,
                             cudaFuncAttributeMaxDynamicSharedMemorySize,
                             (int)smem);
        smem_set = 1;
    }
    scan_kernel<<<BATCH / MBLOCK, MBLOCK, smem>>>(x, a0, out);
}

// round 16
// speedup vs baseline: 1.7395x; 1.3144x over previous
#include <cuda_runtime.h>
#include <math.h>

// HybridEulerIntegrator via tabulated dk(x,a) with windowed a-bin reuse.
// Table: 3072 a-rows (7 mantissa bits/octave, 1536/sign), each row a degree-5
// poly in x on [0,1): C (lower edge) and D = C_next - C, 48B = 3 LDS.128.
// Coeffs pre-scaled by 0.1 = cbrt(0.001).
// Scan: row fetched once per 4-step window; within the window dk is AFFINE in
// true a: dk = A[j] + B[j]*a with A = pc + nb*pd, B = invW*pd precomputed
// off-chain. Body chain per step: FFMA(dk) -> FMUL(dk2) -> FFMA(a) = 12 cyc.
// PF=16 deep x prefetch halves tile-boundary LDG bursts.

#define T_STEPS 2048
#define BATCH   16384
#define HIDDEN  64
#define NROW    3072
#define NFIT    (NROW + 1)
#define NDEG    6
#define PF      16
#define WIN     4

__device__ float  g_nodes[NFIT * NDEG];
__device__ float  g_Cfit[NFIT * NDEG];
__device__ float4 g_tab[3 * NROW];

__device__ __forceinline__ float edge_v7(int k) {
    return exp2f((float)(k >> 7)) * (1.0f + (float)(k & 127) * (1.0f / 128.0f));
}

__device__ __forceinline__ float row_to_a(int r) {
    if (r >= 1536) return  edge_v7(r - 1536) - 1.0f;
    else           return -(edge_v7(1536 - r) - 1.0f);
}

__device__ __forceinline__ float node_x(int node) {
    return 0.5f + 0.5f * cosf((2.0f * node + 1.0f) * (float)M_PI / 12.0f);
}

// ---------------------------------------------------------------------------
__global__ void build_eval_kernel(const float* __restrict__ W1,
                                  const float* __restrict__ b1,
                                  const float* __restrict__ W2,
                                  const float* __restrict__ b2)
{
    const int tid = blockIdx.x * blockDim.x + threadIdx.x;
    if (tid >= NFIT * NDEG) return;
    const int row  = tid / NDEG;
    const int node = tid - row * NDEG;

    const float a = row_to_a(row);
    const float x = node_x(node);

    float acc = b2[0];
    for (int j = 0; j < HIDDEN; j++) {
        float pre = fmaf(W1[j], x, fmaf(W1[HIDDEN + j], a, b1[j]));
        acc = fmaf(W2[j], tanhf(pre), acc);
    }
    g_nodes[tid] = acc;
}

// ---------------------------------------------------------------------------
__global__ void build_fit_kernel()
{
    const int row = blockIdx.x * blockDim.x + threadIdx.x;
    if (row >= NFIT) return;

    float xn[NDEG], v[NDEG];
#pragma unroll
    for (int k = 0; k < NDEG; k++) {
        xn[k] = node_x(k);
        v[k]  = g_nodes[row * NDEG + k];
    }
#pragma unroll
    for (int j = 1; j < NDEG; j++)
#pragma unroll
        for (int i = NDEG - 1; i >= j; i--)
            v[i] = (v[i] - v[i - 1]) / (xn[i] - xn[i - j]);

    float m[NDEG];
    m[0] = v[NDEG - 1];
#pragma unroll
    for (int i = 1; i < NDEG; i++) m[i] = 0.0f;
#pragma unroll
    for (int k = NDEG - 2; k >= 0; k--) {
#pragma unroll
        for (int i = NDEG - 1; i >= 1; i--)
            m[i] = m[i - 1] - xn[k] * m[i];
        m[0] = v[k] - xn[k] * m[0];
    }
#pragma unroll
    for (int i = 0; i < NDEG; i++) g_Cfit[row * NDEG + i] = m[i];
}

// ---------------------------------------------------------------------------
__global__ void build_pack_kernel()
{
    const int i = blockIdx.x * blockDim.x + threadIdx.x;
    if (i >= NROW) return;
    const float S = 0.1f;   // cbrt(0.001)

    float C[NDEG], D[NDEG];
#pragma unroll
    for (int k = 0; k < NDEG; k++) {
        const float c = g_Cfit[i * NDEG + k];
        C[k] = S * c;
        D[k] = S * (g_Cfit[(i + 1) * NDEG + k] - c);
    }
    g_tab[3 * i]     = make_float4(C[0], C[1], C[2], C[3]);
    g_tab[3 * i + 1] = make_float4(C[4], C[5], D[0], D[1]);
    g_tab[3 * i + 2] = make_float4(D[2], D[3], D[4], D[5]);
}

// ---------------------------------------------------------------------------
#define MBLOCK 128

__global__ void __launch_bounds__(MBLOCK)
scan_kernel(const float* __restrict__ x,
            const float* __restrict__ a0,
            float* __restrict__ out)
{
    extern __shared__ float4 sm[];
    for (int i = threadIdx.x; i < 3 * NROW; i += MBLOCK)
        sm[i] = g_tab[i];
    __syncthreads();

    const int e = blockIdx.x * MBLOCK + threadIdx.x;

    float a = a0[e];
    const float* xp = x + e;
    float*       op = out + e;

    float cur[PF], nxt[PF];
#pragma unroll
    for (int k = 0; k < PF; k++)
        cur[k] = __ldg(xp + k * BATCH);

    for (int tb = 0; tb < T_STEPS; tb += PF) {
        if (tb + PF < T_STEPS) {
#pragma unroll
            for (int k = 0; k < PF; k++)
                nxt[k] = __ldg(xp + (PF + k) * BATCH);
        }

#pragma unroll
        for (int w = 0; w < PF; w += WIN) {
            // ---- window head: index + row fetch (amortized over WIN steps) ----
            const float v    = fabsf(a) + 1.0f;
            const int   bits = __float_as_int(v);
            const int   sgn  = __float_as_int(a) >> 31;     // 0 / -1
            int t = bits >> 16;
            t = min(t, 17791);
            const int row = ((t ^ sgn) + (sgn & 32512)) - 14720;

            const float4 P0 = sm[3 * row];
            const float4 P1 = sm[3 * row + 1];
            const float4 P2 = sm[3 * row + 2];

            // Linear model of the lerp fraction in TRUE a (exact at head).
            const float fw   = __int_as_float(((bits & 0xFFFF) << 7) | 0x3F800000) - 1.0f;
            const float fs0  = (sgn != 0) ? (1.0f - fw) : fw;
            const float invW = __int_as_float((261 - (bits >> 23)) << 23);
            const float nb   = fmaf(-a, invW, fs0);

            // Per-step affine pieces (off the a-chain):
            //   dk(a') = A[j] + B[j]*a',  A = pc + nb*pd,  B = invW*pd
            float A[WIN], B[WIN];
#pragma unroll
            for (int j = 0; j < WIN; j++) {
                const float xt = cur[w + j];
                const float xq = xt * xt * xt;
                const float pc = fmaf(fmaf(fmaf(P1.y, xt, P1.x), xt, P0.w), xq,
                                      fmaf(fmaf(P0.z, xt, P0.y), xt, P0.x));
                const float pd = fmaf(fmaf(fmaf(P2.w, xt, P2.z), xt, P2.y), xq,
                                      fmaf(fmaf(P2.x, xt, P1.w), xt, P1.z));
                A[j] = fmaf(nb, pd, pc);
                B[j] = invW * pd;
            }

            // ---- window body: 4 steps, 12-cyc chain each ----
#pragma unroll
            for (int j = 0; j < WIN; j++) {
                const float dk = fmaf(a, B[j], A[j]);     // dk' = 0.1*dk
                const float d2 = dk * dk;
                a = fmaf(d2, dk, a);                      // a += 0.001*dk^3
                op[(w + j) * (size_t)BATCH] = a;
            }
        }

#pragma unroll
        for (int k = 0; k < PF; k++) cur[k] = nxt[k];
        xp += PF * BATCH;
        op += PF * (size_t)BATCH;
    }
}

extern "C" void kernel_launch(void* const* d_in, const int* in_sizes, int n_in,
                              void* d_out, int out_size)
{
    const float* x  = (const float*)d_in[0];
    const float* a0 = (const float*)d_in[1];
    const float* W1 = (const float*)d_in[2];
    const float* b1 = (const float*)d_in[3];
    const float* W2 = (const float*)d_in[4];
    const float* b2 = (const float*)d_in[5];
    float* out = (float*)d_out;

    build_eval_kernel<<<(NFIT * NDEG + 127) / 128, 128>>>(W1, b1, W2, b2);
    build_fit_kernel<<<(NFIT + 127) / 128, 128>>>();
    build_pack_kernel<<<(NROW + 127) / 128, 128>>>();

    const size_t smem = 3u * NROW * sizeof(float4);   // 147456 B
    static int smem_set = 0;
    if (!smem_set) {
        cudaFuncSetAttribute(scan_kernel,
                             cudaFuncAttributeMaxDynamicSharedMemorySize,
                             (int)smem);
        smem_set = 1;
    }
    scan_kernel<<<BATCH / MBLOCK, MBLOCK, smem>>>(x, a0, out);
}

// round 17
// speedup vs baseline: 2.0180x; 1.1601x over previous
#include <cuda_runtime.h>
#include <math.h>

// HybridEulerIntegrator via tabulated dk(x,a), speculative-row pipeline.
// Table: 3072 a-rows (7 mantissa bits/octave, 1536/sign). Row payload (64B):
//   C0..C5 (deg-5 poly in x at lower a-edge, pre-scaled by 0.1=cbrt(0.001)),
//   D0..D5 (= C_next - C, scaled), G = 1/(a_hi-a_lo), H = -a_lo*G.
// fs(a) = G*a + H is GLOBALLY affine in true a for the row, so per-window
// A[j] = pc_j + H*pd_j, B[j] = G*pd_j need no `a` -- they are computed off the
// a-chain from a row fetched SPECULATIVELY (row predicted via apred = 2a-aprev
// at the previous window head). Body chain per step: FFMA -> FMUL -> FFMA.

#define T_STEPS 2048
#define BATCH   16384
#define HIDDEN  64
#define NROW    3072
#define NFIT    (NROW + 1)
#define NDEG    6
#define PF      32
#define WIN     4
#define NWIN    (PF / WIN)

__device__ float  g_nodes[NFIT * NDEG];
__device__ float  g_Cfit[NFIT * NDEG];
__device__ float4 g_tab[4 * NROW];

__device__ __forceinline__ float edge_v7(int k) {
    return exp2f((float)(k >> 7)) * (1.0f + (float)(k & 127) * (1.0f / 128.0f));
}

__device__ __forceinline__ float row_to_a(int r) {
    if (r >= 1536) return  edge_v7(r - 1536) - 1.0f;
    else           return -(edge_v7(1536 - r) - 1.0f);
}

__device__ __forceinline__ float node_x(int node) {
    return 0.5f + 0.5f * cosf((2.0f * node + 1.0f) * (float)M_PI / 12.0f);
}

// ---------------------------------------------------------------------------
__global__ void build_eval_kernel(const float* __restrict__ W1,
                                  const float* __restrict__ b1,
                                  const float* __restrict__ W2,
                                  const float* __restrict__ b2)
{
    const int tid = blockIdx.x * blockDim.x + threadIdx.x;
    if (tid >= NFIT * NDEG) return;
    const int row  = tid / NDEG;
    const int node = tid - row * NDEG;

    const float a = row_to_a(row);
    const float x = node_x(node);

    float acc = b2[0];
    for (int j = 0; j < HIDDEN; j++) {
        float pre = fmaf(W1[j], x, fmaf(W1[HIDDEN + j], a, b1[j]));
        acc = fmaf(W2[j], tanhf(pre), acc);
    }
    g_nodes[tid] = acc;
}

// ---------------------------------------------------------------------------
__global__ void build_fit_kernel()
{
    const int row = blockIdx.x * blockDim.x + threadIdx.x;
    if (row >= NFIT) return;

    float xn[NDEG], v[NDEG];
#pragma unroll
    for (int k = 0; k < NDEG; k++) {
        xn[k] = node_x(k);
        v[k]  = g_nodes[row * NDEG + k];
    }
#pragma unroll
    for (int j = 1; j < NDEG; j++)
#pragma unroll
        for (int i = NDEG - 1; i >= j; i--)
            v[i] = (v[i] - v[i - 1]) / (xn[i] - xn[i - j]);

    float m[NDEG];
    m[0] = v[NDEG - 1];
#pragma unroll
    for (int i = 1; i < NDEG; i++) m[i] = 0.0f;
#pragma unroll
    for (int k = NDEG - 2; k >= 0; k--) {
#pragma unroll
        for (int i = NDEG - 1; i >= 1; i--)
            m[i] = m[i - 1] - xn[k] * m[i];
        m[0] = v[k] - xn[k] * m[0];
    }
#pragma unroll
    for (int i = 0; i < NDEG; i++) g_Cfit[row * NDEG + i] = m[i];
}

// ---------------------------------------------------------------------------
__global__ void build_pack_kernel()
{
    const int i = blockIdx.x * blockDim.x + threadIdx.x;
    if (i >= NROW) return;
    const float S = 0.1f;   // cbrt(0.001)

    float C[NDEG], D[NDEG];
#pragma unroll
    for (int k = 0; k < NDEG; k++) {
        const float c = g_Cfit[i * NDEG + k];
        C[k] = S * c;
        D[k] = S * (g_Cfit[(i + 1) * NDEG + k] - c);
    }
    const float a_lo = row_to_a(i);
    const float a_hi = row_to_a(i + 1);
    const float G = 1.0f / (a_hi - a_lo);
    const float H = -a_lo * G;

    g_tab[4 * i]     = make_float4(C[0], C[1], C[2], C[3]);
    g_tab[4 * i + 1] = make_float4(C[4], C[5], D[0], D[1]);
    g_tab[4 * i + 2] = make_float4(D[2], D[3], D[4], D[5]);
    g_tab[4 * i + 3] = make_float4(G, H, 0.0f, 0.0f);
}

// ---------------------------------------------------------------------------
#define MBLOCK 128

__device__ __forceinline__ int row_index(float ap) {
    const float v    = fabsf(ap) + 1.0f;
    const int   bits = __float_as_int(v);
    const int   sgn  = __float_as_int(ap) >> 31;   // 0 / -1
    int t = bits >> 16;                            // exp + 7 mantissa bits
    t = min(t, 17791);                             // clamp to top bin
    return ((t ^ sgn) + (sgn & 32512)) - 14720;    // 0..3071
}

__global__ void __launch_bounds__(MBLOCK)
scan_kernel(const float* __restrict__ x,
            const float* __restrict__ a0,
            float* __restrict__ out)
{
    extern __shared__ float4 sm[];          // 4 float4 per row
    for (int i = threadIdx.x; i < 4 * NROW; i += MBLOCK)
        sm[i] = g_tab[i];
    __syncthreads();

    const int e = blockIdx.x * MBLOCK + threadIdx.x;

    float a = a0[e];
    const float* xp = x + e;
    float*       op = out + e;

    float cur[PF], nxt[PF];
#pragma unroll
    for (int k = 0; k < PF; k++)
        cur[k] = __ldg(xp + k * BATCH);

    // Prologue: exact row for the initial a; prepare window 0's A/B.
    float A[WIN], B[WIN];
    float aprev = a;
    {
        const int r = row_index(a);
        const float4 R0 = sm[4 * r], R1 = sm[4 * r + 1];
        const float4 R2 = sm[4 * r + 2], R3 = sm[4 * r + 3];
#pragma unroll
        for (int j = 0; j < WIN; j++) {
            const float xt = cur[j];
            const float x3 = xt * xt * xt;
            const float pc = fmaf(fmaf(fmaf(R1.y, xt, R1.x), xt, R0.w), x3,
                                  fmaf(fmaf(R0.z, xt, R0.y), xt, R0.x));
            const float pd = fmaf(fmaf(fmaf(R2.w, xt, R2.z), xt, R2.y), x3,
                                  fmaf(fmaf(R2.x, xt, R1.w), xt, R1.z));
            A[j] = fmaf(R3.y, pd, pc);
            B[j] = R3.x * pd;
        }
    }

    for (int tb = 0; tb < T_STEPS; tb += PF) {
        if (tb + PF < T_STEPS) {
#pragma unroll
            for (int k = 0; k < PF; k++)
                nxt[k] = __ldg(xp + (PF + k) * BATCH);
        }

#pragma unroll
        for (int w = 0; w < NWIN; w++) {
            // Speculative fetch of NEXT window's row (off the chain):
            // apred = linear drift extrapolation; LDS overlaps the body.
            const float apred = 2.0f * a - aprev;
            aprev = a;
            const int r = row_index(apred);
            const float4 R0 = sm[4 * r], R1 = sm[4 * r + 1];
            const float4 R2 = sm[4 * r + 2], R3 = sm[4 * r + 3];

            // ---- body: 4 steps, 12-cyc chain each (A/B prepared earlier) ----
#pragma unroll
            for (int j = 0; j < WIN; j++) {
                const float dk = fmaf(a, B[j], A[j]);    // dk' = 0.1*dk
                const float d2 = dk * dk;
                a = fmaf(d2, dk, a);                     // a += 0.001*dk^3
                op[(w * WIN + j) * (size_t)BATCH] = a;
            }

            // ---- prepare next window's A/B from the speculative row ----
#pragma unroll
            for (int j = 0; j < WIN; j++) {
                const float xt = (w < NWIN - 1) ? cur[w * WIN + WIN + j] : nxt[j];
                const float x3 = xt * xt * xt;
                const float pc = fmaf(fmaf(fmaf(R1.y, xt, R1.x), xt, R0.w), x3,
                                      fmaf(fmaf(R0.z, xt, R0.y), xt, R0.x));
                const float pd = fmaf(fmaf(fmaf(R2.w, xt, R2.z), xt, R2.y), x3,
                                      fmaf(fmaf(R2.x, xt, R1.w), xt, R1.z));
                A[j] = fmaf(R3.y, pd, pc);
                B[j] = R3.x * pd;
            }
        }

#pragma unroll
        for (int k = 0; k < PF; k++) cur[k] = nxt[k];
        xp += PF * BATCH;
        op += PF * (size_t)BATCH;
    }
}

extern "C" void kernel_launch(void* const* d_in, const int* in_sizes, int n_in,
                              void* d_out, int out_size)
{
    const float* x  = (const float*)d_in[0];
    const float* a0 = (const float*)d_in[1];
    const float* W1 = (const float*)d_in[2];
    const float* b1 = (const float*)d_in[3];
    const float* W2 = (const float*)d_in[4];
    const float* b2 = (const float*)d_in[5];
    float* out = (float*)d_out;

    build_eval_kernel<<<(NFIT * NDEG + 127) / 128, 128>>>(W1, b1, W2, b2);
    build_fit_kernel<<<(NFIT + 127) / 128, 128>>>();
    build_pack_kernel<<<(NROW + 127) / 128, 128>>>();

    const size_t smem = 4u * NROW * sizeof(float4);   // 196608 B
    static int smem_set = 0;
    if (!smem_set) {
        cudaFuncSetAttribute(scan_kernel,
                             cudaFuncAttributeMaxDynamicSharedMemorySize,
                             (int)smem);
        smem_set = 1;
    }
    scan_kernel<<<BATCH / MBLOCK, MBLOCK, smem>>>(x, a0, out);
}